// round 8
// baseline (speedup 1.0000x reference)
#include <cuda_runtime.h>
#include <cstdint>

#define BB 8
#define LL 2048
#define DD 512
#define DM 128
#define HH 1024        // L/2
#define RR 512         // r_actual = L - K
#define NU 512         // H - RR (unmerged kept)
#define LO 1536        // NU + HH

typedef unsigned long long ull;

// ---------------- packed f32x2 helpers ----------------
__device__ __forceinline__ void fma2(ull& d, ull a, ull b, ull c) {
    asm("fma.rn.f32x2 %0, %1, %2, %3;" : "=l"(d) : "l"(a), "l"(b), "l"(c));
}
__device__ __forceinline__ ull dup2(float a) {
    ull r;
    asm("mov.b64 %0, {%1, %1};" : "=l"(r) : "f"(a));
    return r;
}
__device__ __forceinline__ void unpack2(float& lo, float& hi, ull v) {
    asm("mov.b64 {%0, %1}, %2;" : "=f"(lo), "=f"(hi) : "l"(v));
}

// ---------------- scratch ----------------
// k-major metric buffers: g_a[(b*DM + k)*HH + token]
__device__ float g_a[BB * DM * HH];
__device__ float g_b[BB * DM * HH];
__device__ float g_pmax[BB * HH * 2];
__device__ int   g_pidx[BB * HH * 2];
__device__ int   g_unm[BB * NU];
__device__ int   g_cnt[BB * HH];
__device__ int   g_off[BB * HH];
__device__ int   g_csr[BB * RR];

// ---------------- metric = normalize(x @ W) ----------------
// 256 threads, tile 128 rows x 128 cols, k-tiles of 32, 8x8 per thread (row-pair packed).
// Per-element accumulation: ascending-k single-accumulator FMA — FROZEN numerics.
// Norm: XLA warp-reduce order — FROZEN.
#define XS 130    // xs_t stride: [32 k][row 0..127]+pad
#define WS 132    // ws stride:   [32 k][col 0..127]+pad
#define NST 132   // norm staging stride
// dynsm floats: max(32*XS + 32*WS, 128*NST) = 16896
__global__ __launch_bounds__(256) void metric_kernel(const float* __restrict__ x,
                                                     const float* __restrict__ W) {
    extern __shared__ float dynsm[];
    __shared__ float norms[128];
    float* xs = dynsm;                 // [32][XS] k-major rows
    float* ws = dynsm + 32 * XS;       // [32][WS] k-major cols

    int tid = threadIdx.x;
    int tx = tid & 15, ty = tid >> 4;  // tx: col group (8 cols), ty: row group (8 rows)
    int rowbase = blockIdx.x * 128;

    ull acc2[4][8];
#pragma unroll
    for (int i = 0; i < 4; i++)
#pragma unroll
        for (int c = 0; c < 8; c++) acc2[i][c] = 0ull;

    const float4* x4 = (const float4*)x;
    const float4* w4 = (const float4*)W;

    for (int kt = 0; kt < 16; kt++) {
        __syncthreads();
        // x tile transposed: 1024 float4, 4/thread
#pragma unroll
        for (int p = 0; p < 4; p++) {
            int idx = p * 256 + tid;
            int r = idx >> 3, q = idx & 7;
            float4 v = x4[(size_t)(rowbase + r) * (DD / 4) + kt * 8 + q];
            xs[(q * 4 + 0) * XS + r] = v.x;
            xs[(q * 4 + 1) * XS + r] = v.y;
            xs[(q * 4 + 2) * XS + r] = v.z;
            xs[(q * 4 + 3) * XS + r] = v.w;
        }
        // W tile natural k-major: 1024 float4, 4/thread
#pragma unroll
        for (int p = 0; p < 4; p++) {
            int idx = p * 256 + tid;
            int k = idx >> 5, q = idx & 31;
            *(float4*)&ws[k * WS + q * 4] = w4[(size_t)(kt * 32 + k) * (DM / 4) + q];
        }
        __syncthreads();
#pragma unroll 8
        for (int k = 0; k < 32; k++) {
            ull ap[4];
#pragma unroll
            for (int i = 0; i < 4; i++)
                ap[i] = *(const ull*)&xs[k * XS + ty * 8 + 2 * i];
            float4 b0 = *(const float4*)&ws[k * WS + tx * 8];
            float4 b1 = *(const float4*)&ws[k * WS + tx * 8 + 4];
            ull bd[8];
            bd[0] = dup2(b0.x); bd[1] = dup2(b0.y); bd[2] = dup2(b0.z); bd[3] = dup2(b0.w);
            bd[4] = dup2(b1.x); bd[5] = dup2(b1.y); bd[6] = dup2(b1.z); bd[7] = dup2(b1.w);
#pragma unroll
            for (int i = 0; i < 4; i++)
#pragma unroll
                for (int c = 0; c < 8; c++)
                    fma2(acc2[i][c], ap[i], bd[c], acc2[i][c]);
        }
    }

    // unpack: val[i][h][c], row = ty*8 + 2i + h, col = tx*8 + c
    float vlo[4][8], vhi[4][8];
#pragma unroll
    for (int i = 0; i < 4; i++)
#pragma unroll
        for (int c = 0; c < 8; c++)
            unpack2(vlo[i][c], vhi[i][c], acc2[i][c]);

    // stage rows to buf for norm
    __syncthreads();
    float* buf = dynsm;   // [128][NST]
#pragma unroll
    for (int i = 0; i < 4; i++) {
        float4 a0 = {vlo[i][0], vlo[i][1], vlo[i][2], vlo[i][3]};
        float4 a1 = {vlo[i][4], vlo[i][5], vlo[i][6], vlo[i][7]};
        float4 b0 = {vhi[i][0], vhi[i][1], vhi[i][2], vhi[i][3]};
        float4 b1 = {vhi[i][4], vhi[i][5], vhi[i][6], vhi[i][7]};
        *(float4*)&buf[(ty * 8 + 2 * i)     * NST + tx * 8]     = a0;
        *(float4*)&buf[(ty * 8 + 2 * i)     * NST + tx * 8 + 4] = a1;
        *(float4*)&buf[(ty * 8 + 2 * i + 1) * NST + tx * 8]     = b0;
        *(float4*)&buf[(ty * 8 + 2 * i + 1) * NST + tx * 8 + 4] = b1;
    }
    __syncthreads();

    if (tid < 128) {
        const float* m = &buf[tid * NST];
        float s[32];
#pragma unroll
        for (int l = 0; l < 32; l++) {
            float t0 = __fmul_rn(m[2 * l],      m[2 * l]);
            float t1 = __fmul_rn(m[2 * l + 1],  m[2 * l + 1]);
            float t2 = __fmul_rn(m[2 * l + 64], m[2 * l + 64]);
            float t3 = __fmul_rn(m[2 * l + 65], m[2 * l + 65]);
            s[l] = __fadd_rn(__fadd_rn(__fadd_rn(t0, t1), t2), t3);
        }
#pragma unroll
        for (int off = 16; off >= 1; off >>= 1)
#pragma unroll
            for (int l = 0; l < 16; l++)
                if (l < off) s[l] = __fadd_rn(s[l], s[l + off]);
        norms[tid] = fmaxf(sqrtf(s[0]), 1e-12f);
    }
    __syncthreads();

    // write k-major outputs: parity h=0 -> g_a, h=1 -> g_b; tokens over i are consecutive
    int b = rowbase >> 11;
    int rb2 = (rowbase & (LL - 1)) >> 1;   // token base in this batch
#pragma unroll
    for (int c = 0; c < 8; c++) {
        int f = tx * 8 + c;
        float4 va, vb;
        va.x = __fdiv_rn(vlo[0][c], norms[ty * 8 + 0]);
        va.y = __fdiv_rn(vlo[1][c], norms[ty * 8 + 2]);
        va.z = __fdiv_rn(vlo[2][c], norms[ty * 8 + 4]);
        va.w = __fdiv_rn(vlo[3][c], norms[ty * 8 + 6]);
        vb.x = __fdiv_rn(vhi[0][c], norms[ty * 8 + 1]);
        vb.y = __fdiv_rn(vhi[1][c], norms[ty * 8 + 3]);
        vb.z = __fdiv_rn(vhi[2][c], norms[ty * 8 + 5]);
        vb.w = __fdiv_rn(vhi[3][c], norms[ty * 8 + 7]);
        size_t o = ((size_t)b * DM + f) * HH + rb2 + ty * 4;
        *(float4*)&g_a[o] = va;
        *(float4*)&g_b[o] = vb;
    }
}

// ---------------- scores = a @ b^T with fused row max/argmax ----------------
// 256 threads; a-tile 128 rows (full K=128 in smem, k-major), 4 chunks of 128 b-cols.
#define SS 132
__global__ __launch_bounds__(256) void scores_kernel(const int* __restrict__ mask) {
    extern __shared__ float sm[];
    float* as = sm;                  // [128 k][SS] a-tokens
    float* bs = sm + 128 * SS;       // [128 k][SS] b-tokens

    int tid = threadIdx.x;
    int tx = tid & 15, ty = tid >> 4;
    int bb   = blockIdx.x >> 4;
    int tile = (blockIdx.x >> 1) & 7;
    int half = blockIdx.x & 1;
    int rowbase = tile * 128;

    const float4* ga4 = (const float4*)g_a;
    const float4* gb4 = (const float4*)g_b;

    // load a-tile: k-major global -> k-major smem, coalesced, conflict-free
#pragma unroll
    for (int p = 0; p < 16; p++) {
        int idx = p * 256 + tid;
        int k = idx >> 5, q = idx & 31;
        *(float4*)&as[k * SS + q * 4] =
            ga4[((size_t)bb * DM + k) * (HH / 4) + (rowbase >> 2) + q];
    }

    float best[8]; int bidx[8];
#pragma unroll
    for (int r = 0; r < 8; r++) { best[r] = -__int_as_float(0x7f800000); bidx[r] = 0; }

    for (int c4 = 0; c4 < 4; c4++) {
        int colbase = (half * 4 + c4) * 128;
        __syncthreads();
#pragma unroll
        for (int p = 0; p < 16; p++) {
            int idx = p * 256 + tid;
            int k = idx >> 5, q = idx & 31;
            *(float4*)&bs[k * SS + q * 4] =
                gb4[((size_t)bb * DM + k) * (HH / 4) + (colbase >> 2) + q];
        }
        __syncthreads();

        ull acc2[4][8];
#pragma unroll
        for (int i = 0; i < 4; i++)
#pragma unroll
            for (int c = 0; c < 8; c++) acc2[i][c] = 0ull;

#pragma unroll 8
        for (int k = 0; k < 128; k++) {
            ull ap[4];
#pragma unroll
            for (int i = 0; i < 4; i++)
                ap[i] = *(const ull*)&as[k * SS + ty * 8 + 2 * i];
            float4 b0 = *(const float4*)&bs[k * SS + tx * 8];
            float4 b1 = *(const float4*)&bs[k * SS + tx * 8 + 4];
            ull bd[8];
            bd[0] = dup2(b0.x); bd[1] = dup2(b0.y); bd[2] = dup2(b0.z); bd[3] = dup2(b0.w);
            bd[4] = dup2(b1.x); bd[5] = dup2(b1.y); bd[6] = dup2(b1.z); bd[7] = dup2(b1.w);
#pragma unroll
            for (int i = 0; i < 4; i++)
#pragma unroll
                for (int c = 0; c < 8; c++)
                    fma2(acc2[i][c], ap[i], bd[c], acc2[i][c]);
        }

        float sc[8][8];   // sc[row 2i+h][col c]
#pragma unroll
        for (int i = 0; i < 4; i++)
#pragma unroll
            for (int c = 0; c < 8; c++)
                unpack2(sc[2 * i][c], sc[2 * i + 1][c], acc2[i][c]);

        bool bm[8];
#pragma unroll
        for (int c = 0; c < 8; c++)
            bm[c] = mask[(size_t)bb * LL + 2 * (colbase + tx * 8 + c) + 1] != 0;

#pragma unroll
        for (int r = 0; r < 8; r++)
#pragma unroll
            for (int c = 0; c < 8; c++) {
                if (bm[c]) {
                    float v = sc[r][c];
                    if (v > best[r]) { best[r] = v; bidx[r] = colbase + tx * 8 + c; }
                }
            }
    }

#pragma unroll
    for (int r = 0; r < 8; r++) {
        if (mask[(size_t)bb * LL + 2 * (rowbase + ty * 8 + r)] == 0) {
            best[r] = -__int_as_float(0x7f800000);
            bidx[r] = 0;
        }
    }

    // reduce across tx (16 candidates/row); exact ties -> lowest column index
    __syncthreads();
    float* rv = as;          // [128][16]
    int*   ri = (int*)bs;    // [128][16]
#pragma unroll
    for (int r = 0; r < 8; r++) {
        rv[(ty * 8 + r) * 16 + tx] = best[r];
        ri[(ty * 8 + r) * 16 + tx] = bidx[r];
    }
    __syncthreads();
    if (tid < 128) {
        float bv = rv[tid * 16]; int bi = ri[tid * 16];
        for (int t = 1; t < 16; t++) {
            float v = rv[tid * 16 + t]; int ii = ri[tid * 16 + t];
            if (v > bv || (v == bv && ii < bi)) { bv = v; bi = ii; }
        }
        size_t o = ((size_t)bb * HH + rowbase + tid) * 2 + half;
        g_pmax[o] = bv;
        g_pidx[o] = bi;
    }
}

// ---------------- combine + register bitonic sort + CSR build ----------------
__device__ __forceinline__ ull cmpx(ull a, ull p, bool takeMin) {
    return takeMin ? (a < p ? a : p) : (a > p ? a : p);
}
__global__ __launch_bounds__(512) void sort_kernel() {
    __shared__ ull sk[HH];
    __shared__ int nidx[HH];
    __shared__ int cnt[HH];
    __shared__ int off[HH];
    int b = blockIdx.x, tid = threadIdx.x;
    int e0 = 2 * tid, e1 = 2 * tid + 1;

    ull k0, k1;
#pragma unroll
    for (int c = 0; c < 2; c++) {
        int t = e0 + c;
        size_t o = ((size_t)b * HH + t) * 2;
        float v0 = g_pmax[o], v1 = g_pmax[o + 1];
        int i0 = g_pidx[o], i1 = g_pidx[o + 1];
        float v; int ii;
        if (v1 > v0) { v = v1; ii = i1; } else { v = v0; ii = i0; }
        nidx[t] = ii;
        unsigned u = __float_as_uint(v);
        u = (u & 0x80000000u) ? ~u : (u | 0x80000000u);
        ull key = ((ull)(~u) << 32) | (unsigned)t;
        if (c == 0) k0 = key; else k1 = key;
    }
    __syncthreads();

    for (int k = 2; k <= HH; k <<= 1) {
        bool up = ((e0 & k) == 0);
        for (int j = k >> 1; j >= 64; j >>= 1) {
            sk[e0] = k0; sk[e1] = k1;
            __syncthreads();
            ull p0 = sk[e0 ^ j], p1 = sk[e1 ^ j];
            bool takeMin = (up == ((e0 & j) == 0));
            k0 = cmpx(k0, p0, takeMin);
            k1 = cmpx(k1, p1, takeMin);
            __syncthreads();
        }
        int jstart = ((k >> 1) < 32) ? (k >> 1) : 32;
        for (int j = jstart; j >= 2; j >>= 1) {
            ull p0 = __shfl_xor_sync(0xffffffffu, k0, j >> 1);
            ull p1 = __shfl_xor_sync(0xffffffffu, k1, j >> 1);
            bool takeMin = (up == ((e0 & j) == 0));
            k0 = cmpx(k0, p0, takeMin);
            k1 = cmpx(k1, p1, takeMin);
        }
        {
            ull lo = k0 < k1 ? k0 : k1;
            ull hi = k0 < k1 ? k1 : k0;
            k0 = up ? lo : hi;
            k1 = up ? hi : lo;
        }
    }

    int tok0 = (int)(k0 & 0xFFFFFFFFu);
    int tok1 = (int)(k1 & 0xFFFFFFFFu);
    if (e0 >= RR) g_unm[b * NU + (e0 - RR)] = tok0;
    if (e1 >= RR) g_unm[b * NU + (e1 - RR)] = tok1;

    // ---- CSR build: dst -> list of src tokens ----
    cnt[e0] = 0; cnt[e1] = 0;
    __syncthreads();
    int d0 = -1, d1 = -1;
    if (e0 < RR) { d0 = nidx[tok0]; atomicAdd(&cnt[d0], 1); }
    if (e1 < RR) { d1 = nidx[tok1]; atomicAdd(&cnt[d1], 1); }
    __syncthreads();
    // inclusive scan (Hillis-Steele) in sk reinterpreted as two int[1024] buffers
    int* bufA = (int*)sk;
    int* bufB = bufA + HH;
    bufA[e0] = cnt[e0]; bufA[e1] = cnt[e1];
    __syncthreads();
    for (int d = 1; d < HH; d <<= 1) {
        for (int t = tid; t < HH; t += 512)
            bufB[t] = bufA[t] + (t >= d ? bufA[t - d] : 0);
        __syncthreads();
        int* tmp = bufA; bufA = bufB; bufB = tmp;
    }
    for (int t = tid; t < HH; t += 512) {
        int ex = bufA[t] - cnt[t];
        off[t] = ex;
        g_cnt[b * HH + t] = cnt[t];
        g_off[b * HH + t] = ex;
        bufB[t] = 0;   // working counters
    }
    __syncthreads();
    if (e0 < RR) { int pos = off[d0] + atomicAdd(&bufB[d0], 1); g_csr[b * RR + pos] = tok0; }
    if (e1 < RR) { int pos = off[d1] + atomicAdd(&bufB[d1], 1); g_csr[b * RR + pos] = tok1; }
}

// ---------------- fused assembly: gather + merge-sum + divide + source ones ----------------
__global__ __launch_bounds__(256) void assemble_kernel(const float* __restrict__ x,
                                                       float* __restrict__ out) {
    int w = (blockIdx.x * 256 + threadIdx.x) >> 5;   // 0..12287
    int lane = threadIdx.x & 31;
    int b = w / LO, k = w % LO;
    float* osrc = out + (size_t)BB * LO * DD;

    if (k < NU) {
        int t = g_unm[b * NU + k];
        const float4* src = (const float4*)(x + ((size_t)b * LL + 2 * t) * DD);
        float4* dst = (float4*)(out + ((size_t)b * LO + k) * DD);
#pragma unroll
        for (int p = 0; p < 4; p++) dst[lane + 32 * p] = src[lane + 32 * p];
        if (lane == 0)
            osrc[((size_t)b * LO + k) * LL + 2 * t] = 1.0f;
    } else {
        int j = k - NU;
        const float4* base = (const float4*)(x + ((size_t)b * LL + 2 * j + 1) * DD);
        float4 v[4];
#pragma unroll
        for (int p = 0; p < 4; p++) v[p] = base[lane + 32 * p];
        int c = g_cnt[b * HH + j];
        int o = g_off[b * HH + j];
        for (int i = 0; i < c; i++) {
            int s = g_csr[b * RR + o + i];
            const float4* sr = (const float4*)(x + ((size_t)b * LL + 2 * s) * DD);
#pragma unroll
            for (int p = 0; p < 4; p++) {
                float4 u = sr[lane + 32 * p];
                v[p].x = __fadd_rn(v[p].x, u.x);
                v[p].y = __fadd_rn(v[p].y, u.y);
                v[p].z = __fadd_rn(v[p].z, u.z);
                v[p].w = __fadd_rn(v[p].w, u.w);
            }
        }
        if (c > 0) {
            float den = (float)(c + 1);
#pragma unroll
            for (int p = 0; p < 4; p++) {
                v[p].x = __fdiv_rn(v[p].x, den);
                v[p].y = __fdiv_rn(v[p].y, den);
                v[p].z = __fdiv_rn(v[p].z, den);
                v[p].w = __fdiv_rn(v[p].w, den);
            }
        }
        float4* dst = (float4*)(out + ((size_t)b * LO + k) * DD);
#pragma unroll
        for (int p = 0; p < 4; p++) dst[lane + 32 * p] = v[p];

        float* srow = &osrc[((size_t)b * LO + k) * LL];
        if (lane == 0) srow[2 * j + 1] = 1.0f;
        for (int i = lane; i < c; i += 32)
            srow[2 * g_csr[b * RR + o + i]] = 1.0f;
    }
}

// ---------------- launch ----------------
extern "C" void kernel_launch(void* const* d_in, const int* in_sizes, int n_in,
                              void* d_out, int out_size) {
    const float* x = (const float*)d_in[0];
    const float* W = (const float*)d_in[1];
    const int* mask = (const int*)d_in[2];
    float* out = (float*)d_out;

    (void)in_sizes; (void)n_in; (void)out_size;

    static cudaStream_t s2 = nullptr;
    static cudaEvent_t evFork = nullptr, evJoin = nullptr;
    static bool attrs_set = false;
    if (!s2) {
        cudaStreamCreateWithFlags(&s2, cudaStreamNonBlocking);
        cudaEventCreateWithFlags(&evFork, cudaEventDisableTiming);
        cudaEventCreateWithFlags(&evJoin, cudaEventDisableTiming);
    }
    int metric_smem = 16896 * (int)sizeof(float);                 // 67584 B
    int scores_smem = 2 * 128 * SS * (int)sizeof(float);          // 135168 B
    if (!attrs_set) {
        cudaFuncSetAttribute(metric_kernel, cudaFuncAttributeMaxDynamicSharedMemorySize,
                             metric_smem);
        cudaFuncSetAttribute(scores_kernel, cudaFuncAttributeMaxDynamicSharedMemorySize,
                             scores_smem);
        attrs_set = true;
    }

    // fork: zero the 100MB source region on s2, overlapped with the FMA-bound GEMMs
    cudaEventRecord(evFork, 0);
    cudaStreamWaitEvent(s2, evFork, 0);
    cudaMemsetAsync(out + (size_t)BB * LO * DD, 0,
                    (size_t)BB * LO * LL * sizeof(float), s2);
    cudaEventRecord(evJoin, s2);

    metric_kernel<<<(BB * LL) / 128, 256, metric_smem>>>(x, W);
    scores_kernel<<<BB * 8 * 2, 256, scores_smem>>>(mask);
    sort_kernel<<<BB, 512>>>();

    cudaStreamWaitEvent(0, evJoin, 0);
    assemble_kernel<<<BB * LO / 8, 256>>>(x, out);
}

// round 9
// speedup vs baseline: 1.2179x; 1.2179x over previous
#include <cuda_runtime.h>
#include <cstdint>

#define BB 8
#define LL 2048
#define DD 512
#define DM 128
#define HH 1024        // L/2
#define RR 512         // r_actual = L - K
#define NU 512         // H - RR (unmerged kept)
#define LO 1536        // NU + HH

typedef unsigned long long ull;

// ---------------- packed f32x2 helpers ----------------
__device__ __forceinline__ void fma2(ull& d, ull a, ull b, ull c) {
    asm("fma.rn.f32x2 %0, %1, %2, %3;" : "=l"(d) : "l"(a), "l"(b), "l"(c));
}
__device__ __forceinline__ ull dup2(float a) {
    ull r;
    asm("mov.b64 %0, {%1, %1};" : "=l"(r) : "f"(a));
    return r;
}
__device__ __forceinline__ void unpack2(float& lo, float& hi, ull v) {
    asm("mov.b64 {%0, %1}, %2;" : "=f"(lo), "=f"(hi) : "l"(v));
}

// ---------------- scratch ----------------
__device__ float g_a[BB * HH * DM];          // normalized metric, even tokens (token-major)
__device__ float g_b[BB * HH * DM];          // normalized metric, odd tokens
__device__ float g_pmax[BB * HH * 2];
__device__ int   g_pidx[BB * HH * 2];
__device__ int   g_unm[BB * NU];
__device__ int   g_cnt[BB * HH];
__device__ int   g_off[BB * HH];
__device__ int   g_csr[BB * RR];

// ---------------- metric = normalize(x @ W)  (round-6 version, 167.5us config) ----------------
#define XST 36
#define WST 132
#define NST 129
__global__ __launch_bounds__(512) void metric_kernel(const float* __restrict__ x,
                                                     const float* __restrict__ W) {
    extern __shared__ float dynsm[];        // 128*NST floats (covers GEMM tiles)
    __shared__ float norms[128];
    float* xs = dynsm;                       // [128][XST]
    float* ws = dynsm + 128 * XST;           // [32][WST]

    int tid = threadIdx.x;
    int tx = tid & 31, ty = tid >> 5;
    int rowbase = blockIdx.x * 128;

    ull acc2[8][2];
#pragma unroll
    for (int i = 0; i < 8; i++) { acc2[i][0] = 0ull; acc2[i][1] = 0ull; }

    const float4* x4 = (const float4*)x;
    const float4* w4 = (const float4*)W;

    for (int kt = 0; kt < 16; kt++) {
        __syncthreads();
#pragma unroll
        for (int p = 0; p < 2; p++) {
            int idx = p * 512 + tid;
            int r = idx >> 3, q = idx & 7;
            *(float4*)&xs[r * XST + q * 4] = x4[(size_t)(rowbase + r) * (DD / 4) + kt * 8 + q];
        }
#pragma unroll
        for (int p = 0; p < 2; p++) {
            int idx = p * 512 + tid;
            int k = idx >> 5, q = idx & 31;
            *(float4*)&ws[k * WST + q * 4] = w4[(size_t)(kt * 32 + k) * (DM / 4) + q];
        }
        __syncthreads();
#pragma unroll
        for (int k4 = 0; k4 < 8; k4++) {
            float4 af[8];
#pragma unroll
            for (int i = 0; i < 8; i++)
                af[i] = *(const float4*)&xs[(ty * 8 + i) * XST + k4 * 4];
#pragma unroll
            for (int kk = 0; kk < 4; kk++) {
                ulonglong2 b2 = *(const ulonglong2*)&ws[(k4 * 4 + kk) * WST + tx * 4];
#pragma unroll
                for (int i = 0; i < 8; i++) {
                    float a = (kk == 0) ? af[i].x : (kk == 1) ? af[i].y : (kk == 2) ? af[i].z : af[i].w;
                    ull a2 = dup2(a);
                    fma2(acc2[i][0], a2, b2.x, acc2[i][0]);
                    fma2(acc2[i][1], a2, b2.y, acc2[i][1]);
                }
            }
        }
    }

    float acc[8][4];
#pragma unroll
    for (int i = 0; i < 8; i++) {
        unpack2(acc[i][0], acc[i][1], acc2[i][0]);
        unpack2(acc[i][2], acc[i][3], acc2[i][1]);
    }

    __syncthreads();
    float* buf = dynsm;   // [128 rows][NST]
#pragma unroll
    for (int i = 0; i < 8; i++)
#pragma unroll
        for (int c = 0; c < 4; c++)
            buf[(ty * 8 + i) * NST + tx * 4 + c] = acc[i][c];
    __syncthreads();

    if (tid < 128) {
        const float* m = &buf[tid * NST];
        float s[32];
#pragma unroll
        for (int l = 0; l < 32; l++) {
            float t0 = __fmul_rn(m[2 * l],      m[2 * l]);
            float t1 = __fmul_rn(m[2 * l + 1],  m[2 * l + 1]);
            float t2 = __fmul_rn(m[2 * l + 64], m[2 * l + 64]);
            float t3 = __fmul_rn(m[2 * l + 65], m[2 * l + 65]);
            s[l] = __fadd_rn(__fadd_rn(__fadd_rn(t0, t1), t2), t3);
        }
#pragma unroll
        for (int off = 16; off >= 1; off >>= 1)
#pragma unroll
            for (int l = 0; l < 16; l++)
                if (l < off) s[l] = __fadd_rn(s[l], s[l + off]);
        norms[tid] = fmaxf(sqrtf(s[0]), 1e-12f);
    }
    __syncthreads();

#pragma unroll
    for (int i = 0; i < 8; i++) {
        int trow = rowbase + ty * 8 + i;
        int b = trow >> 11;
        int l = trow & (LL - 1);
        float n = norms[ty * 8 + i];
        float* dstbase = ((l & 1) ? g_b : g_a) + ((size_t)b * HH + (l >> 1)) * DM;
        float4 v;
        v.x = __fdiv_rn(acc[i][0], n); v.y = __fdiv_rn(acc[i][1], n);
        v.z = __fdiv_rn(acc[i][2], n); v.w = __fdiv_rn(acc[i][3], n);
        *(float4*)&dstbase[tx * 4] = v;
    }
}

// ---------------- scores = a @ b^T with fused row max/argmax (round-6 version) ----------------
#define AST2 132
#define BST2 132
__global__ __launch_bounds__(512) void scores_kernel(const int* __restrict__ mask) {
    extern __shared__ float sm[];
    float* as = sm;                  // [128][AST2]
    float* bs = sm + 128 * AST2;     // [128][BST2]  (k-major)

    int tid = threadIdx.x;
    int tx = tid & 31, ty = tid >> 5;
    int bb   = blockIdx.x >> 4;
    int tile = (blockIdx.x >> 1) & 7;
    int half = blockIdx.x & 1;
    int rowbase = tile * 128;

    const float4* ga = (const float4*)(g_a + ((size_t)bb * HH + rowbase) * DM);
#pragma unroll
    for (int p = 0; p < 8; p++) {
        int idx = p * 512 + tid;
        int r = idx >> 5, q = idx & 31;
        *(float4*)&as[r * AST2 + q * 4] = ga[(size_t)r * 32 + q];
    }

    float best[8]; int bidx[8];
#pragma unroll
    for (int i = 0; i < 8; i++) { best[i] = -__int_as_float(0x7f800000); bidx[i] = 0; }

    for (int c4 = 0; c4 < 4; c4++) {
        int ch = half * 4 + c4;
        __syncthreads();
        const float4* gb = (const float4*)(g_b + ((size_t)bb * HH + ch * 128) * DM);
#pragma unroll
        for (int p = 0; p < 8; p++) {
            int idx = p * 512 + tid;
            int tok = idx >> 5, q = idx & 31;
            float4 v = gb[(size_t)tok * 32 + q];
            bs[(q * 4 + 0) * BST2 + tok] = v.x;
            bs[(q * 4 + 1) * BST2 + tok] = v.y;
            bs[(q * 4 + 2) * BST2 + tok] = v.z;
            bs[(q * 4 + 3) * BST2 + tok] = v.w;
        }
        __syncthreads();

        ull acc2[8][2];
#pragma unroll
        for (int i = 0; i < 8; i++) { acc2[i][0] = 0ull; acc2[i][1] = 0ull; }

#pragma unroll
        for (int k4 = 0; k4 < 32; k4++) {
            float4 af[8];
#pragma unroll
            for (int i = 0; i < 8; i++)
                af[i] = *(const float4*)&as[(ty * 8 + i) * AST2 + k4 * 4];
#pragma unroll
            for (int kk = 0; kk < 4; kk++) {
                ulonglong2 b2 = *(const ulonglong2*)&bs[(k4 * 4 + kk) * BST2 + tx * 4];
#pragma unroll
                for (int i = 0; i < 8; i++) {
                    float a = (kk == 0) ? af[i].x : (kk == 1) ? af[i].y : (kk == 2) ? af[i].z : af[i].w;
                    ull a2 = dup2(a);
                    fma2(acc2[i][0], a2, b2.x, acc2[i][0]);
                    fma2(acc2[i][1], a2, b2.y, acc2[i][1]);
                }
            }
        }

        float acc[8][4];
#pragma unroll
        for (int i = 0; i < 8; i++) {
            unpack2(acc[i][0], acc[i][1], acc2[i][0]);
            unpack2(acc[i][2], acc[i][3], acc2[i][1]);
        }

        bool bm[4];
#pragma unroll
        for (int c = 0; c < 4; c++)
            bm[c] = mask[(size_t)bb * LL + 2 * (ch * 128 + tx * 4 + c) + 1] != 0;

#pragma unroll
        for (int i = 0; i < 8; i++)
#pragma unroll
            for (int c = 0; c < 4; c++) {
                if (bm[c]) {
                    float v = acc[i][c];
                    if (v > best[i]) { best[i] = v; bidx[i] = ch * 128 + tx * 4 + c; }
                }
            }
    }

#pragma unroll
    for (int i = 0; i < 8; i++) {
        if (mask[(size_t)bb * LL + 2 * (rowbase + ty * 8 + i)] == 0) {
            best[i] = -__int_as_float(0x7f800000);
            bidx[i] = 0;
        }
    }

    __syncthreads();
    float* rv = as;
    int*   ri = (int*)bs;
#pragma unroll
    for (int i = 0; i < 8; i++) {
        rv[(ty * 8 + i) * 32 + tx] = best[i];
        ri[(ty * 8 + i) * 32 + tx] = bidx[i];
    }
    __syncthreads();
    if (tid < 128) {
        float bv = rv[tid * 32]; int bi = ri[tid * 32];
        for (int t = 1; t < 32; t++) {
            float v = rv[tid * 32 + t]; int ii = ri[tid * 32 + t];
            if (v > bv || (v == bv && ii < bi)) { bv = v; bi = ii; }
        }
        size_t o = ((size_t)bb * HH + rowbase + tid) * 2 + half;
        g_pmax[o] = bv;
        g_pidx[o] = bi;
    }
}

// ---------------- combine + register bitonic sort + CSR build ----------------
__device__ __forceinline__ ull cmpx(ull a, ull p, bool takeMin) {
    return takeMin ? (a < p ? a : p) : (a > p ? a : p);
}
__global__ __launch_bounds__(512) void sort_kernel() {
    __shared__ ull sk[HH];
    __shared__ int nidx[HH];
    __shared__ int cnt[HH];
    __shared__ int off[HH];
    int b = blockIdx.x, tid = threadIdx.x;
    int e0 = 2 * tid, e1 = 2 * tid + 1;

    ull k0, k1;
#pragma unroll
    for (int c = 0; c < 2; c++) {
        int t = e0 + c;
        size_t o = ((size_t)b * HH + t) * 2;
        float v0 = g_pmax[o], v1 = g_pmax[o + 1];
        int i0 = g_pidx[o], i1 = g_pidx[o + 1];
        float v; int ii;
        if (v1 > v0) { v = v1; ii = i1; } else { v = v0; ii = i0; }
        nidx[t] = ii;
        unsigned u = __float_as_uint(v);
        u = (u & 0x80000000u) ? ~u : (u | 0x80000000u);
        ull key = ((ull)(~u) << 32) | (unsigned)t;
        if (c == 0) k0 = key; else k1 = key;
    }
    __syncthreads();

    for (int k = 2; k <= HH; k <<= 1) {
        bool up = ((e0 & k) == 0);
        for (int j = k >> 1; j >= 64; j >>= 1) {
            sk[e0] = k0; sk[e1] = k1;
            __syncthreads();
            ull p0 = sk[e0 ^ j], p1 = sk[e1 ^ j];
            bool takeMin = (up == ((e0 & j) == 0));
            k0 = cmpx(k0, p0, takeMin);
            k1 = cmpx(k1, p1, takeMin);
            __syncthreads();
        }
        int jstart = ((k >> 1) < 32) ? (k >> 1) : 32;
        for (int j = jstart; j >= 2; j >>= 1) {
            ull p0 = __shfl_xor_sync(0xffffffffu, k0, j >> 1);
            ull p1 = __shfl_xor_sync(0xffffffffu, k1, j >> 1);
            bool takeMin = (up == ((e0 & j) == 0));
            k0 = cmpx(k0, p0, takeMin);
            k1 = cmpx(k1, p1, takeMin);
        }
        {
            ull lo = k0 < k1 ? k0 : k1;
            ull hi = k0 < k1 ? k1 : k0;
            k0 = up ? lo : hi;
            k1 = up ? hi : lo;
        }
    }

    int tok0 = (int)(k0 & 0xFFFFFFFFu);
    int tok1 = (int)(k1 & 0xFFFFFFFFu);
    if (e0 >= RR) g_unm[b * NU + (e0 - RR)] = tok0;
    if (e1 >= RR) g_unm[b * NU + (e1 - RR)] = tok1;

    // ---- CSR build: dst -> list of src tokens ----
    cnt[e0] = 0; cnt[e1] = 0;
    __syncthreads();
    int d0 = -1, d1 = -1;
    if (e0 < RR) { d0 = nidx[tok0]; atomicAdd(&cnt[d0], 1); }
    if (e1 < RR) { d1 = nidx[tok1]; atomicAdd(&cnt[d1], 1); }
    __syncthreads();
    int* bufA = (int*)sk;
    int* bufB = bufA + HH;
    bufA[e0] = cnt[e0]; bufA[e1] = cnt[e1];
    __syncthreads();
    for (int d = 1; d < HH; d <<= 1) {
        for (int t = tid; t < HH; t += 512)
            bufB[t] = bufA[t] + (t >= d ? bufA[t - d] : 0);
        __syncthreads();
        int* tmp = bufA; bufA = bufB; bufB = tmp;
    }
    for (int t = tid; t < HH; t += 512) {
        int ex = bufA[t] - cnt[t];
        off[t] = ex;
        g_cnt[b * HH + t] = cnt[t];
        g_off[b * HH + t] = ex;
        bufB[t] = 0;
    }
    __syncthreads();
    if (e0 < RR) { int pos = off[d0] + atomicAdd(&bufB[d0], 1); g_csr[b * RR + pos] = tok0; }
    if (e1 < RR) { int pos = off[d1] + atomicAdd(&bufB[d1], 1); g_csr[b * RR + pos] = tok1; }
}

// ---------------- fused assembly: gather + merge-sum + divide + source ones ----------------
__global__ __launch_bounds__(256) void assemble_kernel(const float* __restrict__ x,
                                                       float* __restrict__ out) {
    int w = (blockIdx.x * 256 + threadIdx.x) >> 5;   // 0..12287
    int lane = threadIdx.x & 31;
    int b = w / LO, k = w % LO;
    float* osrc = out + (size_t)BB * LO * DD;

    if (k < NU) {
        int t = g_unm[b * NU + k];
        const float4* src = (const float4*)(x + ((size_t)b * LL + 2 * t) * DD);
        float4* dst = (float4*)(out + ((size_t)b * LO + k) * DD);
#pragma unroll
        for (int p = 0; p < 4; p++) dst[lane + 32 * p] = src[lane + 32 * p];
        if (lane == 0)
            osrc[((size_t)b * LO + k) * LL + 2 * t] = 1.0f;
    } else {
        int j = k - NU;
        const float4* base = (const float4*)(x + ((size_t)b * LL + 2 * j + 1) * DD);
        float4 v[4];
#pragma unroll
        for (int p = 0; p < 4; p++) v[p] = base[lane + 32 * p];
        int c = g_cnt[b * HH + j];
        int o = g_off[b * HH + j];
        for (int i = 0; i < c; i++) {
            int s = g_csr[b * RR + o + i];
            const float4* sr = (const float4*)(x + ((size_t)b * LL + 2 * s) * DD);
#pragma unroll
            for (int p = 0; p < 4; p++) {
                float4 u = sr[lane + 32 * p];
                v[p].x = __fadd_rn(v[p].x, u.x);
                v[p].y = __fadd_rn(v[p].y, u.y);
                v[p].z = __fadd_rn(v[p].z, u.z);
                v[p].w = __fadd_rn(v[p].w, u.w);
            }
        }
        if (c > 0) {
            float den = (float)(c + 1);
#pragma unroll
            for (int p = 0; p < 4; p++) {
                v[p].x = __fdiv_rn(v[p].x, den);
                v[p].y = __fdiv_rn(v[p].y, den);
                v[p].z = __fdiv_rn(v[p].z, den);
                v[p].w = __fdiv_rn(v[p].w, den);
            }
        }
        float4* dst = (float4*)(out + ((size_t)b * LO + k) * DD);
#pragma unroll
        for (int p = 0; p < 4; p++) dst[lane + 32 * p] = v[p];

        float* srow = &osrc[((size_t)b * LO + k) * LL];
        if (lane == 0) srow[2 * j + 1] = 1.0f;
        for (int i = lane; i < c; i += 32)
            srow[2 * g_csr[b * RR + o + i]] = 1.0f;
    }
}

// ---------------- launch ----------------
extern "C" void kernel_launch(void* const* d_in, const int* in_sizes, int n_in,
                              void* d_out, int out_size) {
    const float* x = (const float*)d_in[0];
    const float* W = (const float*)d_in[1];
    const int* mask = (const int*)d_in[2];
    float* out = (float*)d_out;

    (void)in_sizes; (void)n_in; (void)out_size;

    static cudaStream_t s2 = nullptr;
    static cudaEvent_t evFork = nullptr, evJoin = nullptr;
    static bool attrs_set = false;
    if (!s2) {
        cudaStreamCreateWithFlags(&s2, cudaStreamNonBlocking);
        cudaEventCreateWithFlags(&evFork, cudaEventDisableTiming);
        cudaEventCreateWithFlags(&evJoin, cudaEventDisableTiming);
    }
    int metric_smem = 128 * NST * (int)sizeof(float);                 // 66048 B
    int scores_smem = (128 * AST2 + 128 * BST2) * (int)sizeof(float); // 135168 B
    if (!attrs_set) {
        cudaFuncSetAttribute(metric_kernel, cudaFuncAttributeMaxDynamicSharedMemorySize,
                             metric_smem);
        cudaFuncSetAttribute(scores_kernel, cudaFuncAttributeMaxDynamicSharedMemorySize,
                             scores_smem);
        attrs_set = true;
    }

    // fork: zero the 100MB source region on s2, overlapped with the FMA-bound GEMMs
    cudaEventRecord(evFork, 0);
    cudaStreamWaitEvent(s2, evFork, 0);
    cudaMemsetAsync(out + (size_t)BB * LO * DD, 0,
                    (size_t)BB * LO * LL * sizeof(float), s2);
    cudaEventRecord(evJoin, s2);

    metric_kernel<<<(BB * LL) / 128, 512, metric_smem>>>(x, W);
    scores_kernel<<<BB * 8 * 2, 512, scores_smem>>>(mask);
    sort_kernel<<<BB, 512>>>();

    cudaStreamWaitEvent(0, evJoin, 0);
    assemble_kernel<<<BB * LO / 8, 256>>>(x, out);
}

// round 10
// speedup vs baseline: 1.2931x; 1.0617x over previous
#include <cuda_runtime.h>
#include <cstdint>

#define BB 8
#define LL 2048
#define DD 512
#define DM 128
#define HH 1024        // L/2
#define RR 512         // r_actual = L - K
#define NU 512         // H - RR (unmerged kept)
#define LO 1536        // NU + HH

typedef unsigned long long ull;

// ---------------- packed f32x2 helpers ----------------
__device__ __forceinline__ void fma2(ull& d, ull a, ull b, ull c) {
    asm("fma.rn.f32x2 %0, %1, %2, %3;" : "=l"(d) : "l"(a), "l"(b), "l"(c));
}
__device__ __forceinline__ ull dup2(float a) {
    ull r;
    asm("mov.b64 %0, {%1, %1};" : "=l"(r) : "f"(a));
    return r;
}
__device__ __forceinline__ void unpack2(float& lo, float& hi, ull v) {
    asm("mov.b64 {%0, %1}, %2;" : "=f"(lo), "=f"(hi) : "l"(v));
}

// ---------------- scratch ----------------
__device__ float g_a[BB * HH * DM];          // normalized metric, even tokens (token-major)
__device__ float g_b[BB * HH * DM];          // normalized metric, odd tokens
__device__ float g_pmax[BB * HH * 2];
__device__ int   g_pidx[BB * HH * 2];
__device__ int   g_unm[BB * NU];
__device__ int   g_cnt[BB * HH];
__device__ int   g_off[BB * HH];
__device__ int   g_csr[BB * RR];

// ---------------- metric = normalize(x @ W)  — double-buffered k-tiles ----------------
#define XST 36
#define WST 132
#define NST 129
#define TILE_F (128 * XST + 32 * WST)   // 8832 floats per buffer
__global__ __launch_bounds__(512) void metric_kernel(const float* __restrict__ x,
                                                     const float* __restrict__ W) {
    extern __shared__ float dynsm[];        // 2*TILE_F floats
    __shared__ float norms[128];

    int tid = threadIdx.x;
    int tx = tid & 31, ty = tid >> 5;
    int rowbase = blockIdx.x * 128;

    const float4* x4 = (const float4*)x;
    const float4* w4 = (const float4*)W;

    // per-thread load coordinates (invariant across kt)
    int xr[2], xq[2], wk[2], wq[2];
#pragma unroll
    for (int p = 0; p < 2; p++) {
        int idx = p * 512 + tid;
        xr[p] = idx >> 3;  xq[p] = idx & 7;
        wk[p] = idx >> 5;  wq[p] = idx & 31;
    }

    float* buf0 = dynsm;
    float* buf1 = dynsm + TILE_F;

    // preload kt = 0
    {
        float* xs = buf0;
        float* ws = buf0 + 128 * XST;
#pragma unroll
        for (int p = 0; p < 2; p++) {
            *(float4*)&xs[xr[p] * XST + xq[p] * 4] =
                x4[(size_t)(rowbase + xr[p]) * (DD / 4) + xq[p]];
            *(float4*)&ws[wk[p] * WST + wq[p] * 4] =
                w4[(size_t)wk[p] * (DM / 4) + wq[p]];
        }
    }
    __syncthreads();

    ull acc2[8][2];
#pragma unroll
    for (int i = 0; i < 8; i++) { acc2[i][0] = 0ull; acc2[i][1] = 0ull; }

    for (int kt = 0; kt < 16; kt++) {
        float* cb = (kt & 1) ? buf1 : buf0;
        float* nb = (kt & 1) ? buf0 : buf1;

        // prefetch next k-tile into registers (overlaps with compute below)
        float4 px[2], pw[2];
        if (kt < 15) {
#pragma unroll
            for (int p = 0; p < 2; p++) {
                px[p] = x4[(size_t)(rowbase + xr[p]) * (DD / 4) + (kt + 1) * 8 + xq[p]];
                pw[p] = w4[(size_t)((kt + 1) * 32 + wk[p]) * (DM / 4) + wq[p]];
            }
        }

        float* xs = cb;
        float* ws = cb + 128 * XST;
#pragma unroll
        for (int k4 = 0; k4 < 8; k4++) {
            float4 af[8];
#pragma unroll
            for (int i = 0; i < 8; i++)
                af[i] = *(const float4*)&xs[(ty * 8 + i) * XST + k4 * 4];
#pragma unroll
            for (int kk = 0; kk < 4; kk++) {
                ulonglong2 b2 = *(const ulonglong2*)&ws[(k4 * 4 + kk) * WST + tx * 4];
#pragma unroll
                for (int i = 0; i < 8; i++) {
                    float a = (kk == 0) ? af[i].x : (kk == 1) ? af[i].y : (kk == 2) ? af[i].z : af[i].w;
                    ull a2 = dup2(a);
                    fma2(acc2[i][0], a2, b2.x, acc2[i][0]);
                    fma2(acc2[i][1], a2, b2.y, acc2[i][1]);
                }
            }
        }

        if (kt < 15) {
            float* xd = nb;
            float* wd = nb + 128 * XST;
#pragma unroll
            for (int p = 0; p < 2; p++) {
                *(float4*)&xd[xr[p] * XST + xq[p] * 4] = px[p];
                *(float4*)&wd[wk[p] * WST + wq[p] * 4] = pw[p];
            }
        }
        __syncthreads();
    }

    float acc[8][4];
#pragma unroll
    for (int i = 0; i < 8; i++) {
        unpack2(acc[i][0], acc[i][1], acc2[i][0]);
        unpack2(acc[i][2], acc[i][3], acc2[i][1]);
    }

    float* buf = dynsm;   // [128 rows][NST] staging (16512 floats < 2*TILE_F)
#pragma unroll
    for (int i = 0; i < 8; i++)
#pragma unroll
        for (int c = 0; c < 4; c++)
            buf[(ty * 8 + i) * NST + tx * 4 + c] = acc[i][c];
    __syncthreads();

    if (tid < 128) {
        const float* m = &buf[tid * NST];
        float s[32];
#pragma unroll
        for (int l = 0; l < 32; l++) {
            float t0 = __fmul_rn(m[2 * l],      m[2 * l]);
            float t1 = __fmul_rn(m[2 * l + 1],  m[2 * l + 1]);
            float t2 = __fmul_rn(m[2 * l + 64], m[2 * l + 64]);
            float t3 = __fmul_rn(m[2 * l + 65], m[2 * l + 65]);
            s[l] = __fadd_rn(__fadd_rn(__fadd_rn(t0, t1), t2), t3);
        }
#pragma unroll
        for (int off = 16; off >= 1; off >>= 1)
#pragma unroll
            for (int l = 0; l < 16; l++)
                if (l < off) s[l] = __fadd_rn(s[l], s[l + off]);
        norms[tid] = fmaxf(sqrtf(s[0]), 1e-12f);
    }
    __syncthreads();

#pragma unroll
    for (int i = 0; i < 8; i++) {
        int trow = rowbase + ty * 8 + i;
        int b = trow >> 11;
        int l = trow & (LL - 1);
        float n = norms[ty * 8 + i];
        float* dstbase = ((l & 1) ? g_b : g_a) + ((size_t)b * HH + (l >> 1)) * DM;
        float4 v;
        v.x = __fdiv_rn(acc[i][0], n); v.y = __fdiv_rn(acc[i][1], n);
        v.z = __fdiv_rn(acc[i][2], n); v.w = __fdiv_rn(acc[i][3], n);
        *(float4*)&dstbase[tx * 4] = v;
    }
}

// ---------------- scores = a @ b^T with fused row max/argmax (round-6 version) ----------------
#define AST2 132
#define BST2 132
__global__ __launch_bounds__(512) void scores_kernel(const int* __restrict__ mask) {
    extern __shared__ float sm[];
    float* as = sm;                  // [128][AST2]
    float* bs = sm + 128 * AST2;     // [128][BST2]  (k-major)

    int tid = threadIdx.x;
    int tx = tid & 31, ty = tid >> 5;
    int bb   = blockIdx.x >> 4;
    int tile = (blockIdx.x >> 1) & 7;
    int half = blockIdx.x & 1;
    int rowbase = tile * 128;

    const float4* ga = (const float4*)(g_a + ((size_t)bb * HH + rowbase) * DM);
#pragma unroll
    for (int p = 0; p < 8; p++) {
        int idx = p * 512 + tid;
        int r = idx >> 5, q = idx & 31;
        *(float4*)&as[r * AST2 + q * 4] = ga[(size_t)r * 32 + q];
    }

    float best[8]; int bidx[8];
#pragma unroll
    for (int i = 0; i < 8; i++) { best[i] = -__int_as_float(0x7f800000); bidx[i] = 0; }

    for (int c4 = 0; c4 < 4; c4++) {
        int ch = half * 4 + c4;
        __syncthreads();
        const float4* gb = (const float4*)(g_b + ((size_t)bb * HH + ch * 128) * DM);
#pragma unroll
        for (int p = 0; p < 8; p++) {
            int idx = p * 512 + tid;
            int tok = idx >> 5, q = idx & 31;
            float4 v = gb[(size_t)tok * 32 + q];
            bs[(q * 4 + 0) * BST2 + tok] = v.x;
            bs[(q * 4 + 1) * BST2 + tok] = v.y;
            bs[(q * 4 + 2) * BST2 + tok] = v.z;
            bs[(q * 4 + 3) * BST2 + tok] = v.w;
        }
        __syncthreads();

        ull acc2[8][2];
#pragma unroll
        for (int i = 0; i < 8; i++) { acc2[i][0] = 0ull; acc2[i][1] = 0ull; }

#pragma unroll
        for (int k4 = 0; k4 < 32; k4++) {
            float4 af[8];
#pragma unroll
            for (int i = 0; i < 8; i++)
                af[i] = *(const float4*)&as[(ty * 8 + i) * AST2 + k4 * 4];
#pragma unroll
            for (int kk = 0; kk < 4; kk++) {
                ulonglong2 b2 = *(const ulonglong2*)&bs[(k4 * 4 + kk) * BST2 + tx * 4];
#pragma unroll
                for (int i = 0; i < 8; i++) {
                    float a = (kk == 0) ? af[i].x : (kk == 1) ? af[i].y : (kk == 2) ? af[i].z : af[i].w;
                    ull a2 = dup2(a);
                    fma2(acc2[i][0], a2, b2.x, acc2[i][0]);
                    fma2(acc2[i][1], a2, b2.y, acc2[i][1]);
                }
            }
        }

        float acc[8][4];
#pragma unroll
        for (int i = 0; i < 8; i++) {
            unpack2(acc[i][0], acc[i][1], acc2[i][0]);
            unpack2(acc[i][2], acc[i][3], acc2[i][1]);
        }

        bool bm[4];
#pragma unroll
        for (int c = 0; c < 4; c++)
            bm[c] = mask[(size_t)bb * LL + 2 * (ch * 128 + tx * 4 + c) + 1] != 0;

#pragma unroll
        for (int i = 0; i < 8; i++)
#pragma unroll
            for (int c = 0; c < 4; c++) {
                if (bm[c]) {
                    float v = acc[i][c];
                    if (v > best[i]) { best[i] = v; bidx[i] = ch * 128 + tx * 4 + c; }
                }
            }
    }

#pragma unroll
    for (int i = 0; i < 8; i++) {
        if (mask[(size_t)bb * LL + 2 * (rowbase + ty * 8 + i)] == 0) {
            best[i] = -__int_as_float(0x7f800000);
            bidx[i] = 0;
        }
    }

    __syncthreads();
    float* rv = as;
    int*   ri = (int*)bs;
#pragma unroll
    for (int i = 0; i < 8; i++) {
        rv[(ty * 8 + i) * 32 + tx] = best[i];
        ri[(ty * 8 + i) * 32 + tx] = bidx[i];
    }
    __syncthreads();
    if (tid < 128) {
        float bv = rv[tid * 32]; int bi = ri[tid * 32];
        for (int t = 1; t < 32; t++) {
            float v = rv[tid * 32 + t]; int ii = ri[tid * 32 + t];
            if (v > bv || (v == bv && ii < bi)) { bv = v; bi = ii; }
        }
        size_t o = ((size_t)bb * HH + rowbase + tid) * 2 + half;
        g_pmax[o] = bv;
        g_pidx[o] = bi;
    }
}

// ---------------- combine + register bitonic sort + CSR build ----------------
__device__ __forceinline__ ull cmpx(ull a, ull p, bool takeMin) {
    return takeMin ? (a < p ? a : p) : (a > p ? a : p);
}
__global__ __launch_bounds__(512) void sort_kernel() {
    __shared__ ull sk[HH];
    __shared__ int nidx[HH];
    __shared__ int cnt[HH];
    __shared__ int off[HH];
    int b = blockIdx.x, tid = threadIdx.x;
    int e0 = 2 * tid, e1 = 2 * tid + 1;

    ull k0, k1;
#pragma unroll
    for (int c = 0; c < 2; c++) {
        int t = e0 + c;
        size_t o = ((size_t)b * HH + t) * 2;
        float v0 = g_pmax[o], v1 = g_pmax[o + 1];
        int i0 = g_pidx[o], i1 = g_pidx[o + 1];
        float v; int ii;
        if (v1 > v0) { v = v1; ii = i1; } else { v = v0; ii = i0; }
        nidx[t] = ii;
        unsigned u = __float_as_uint(v);
        u = (u & 0x80000000u) ? ~u : (u | 0x80000000u);
        ull key = ((ull)(~u) << 32) | (unsigned)t;
        if (c == 0) k0 = key; else k1 = key;
    }
    __syncthreads();

    for (int k = 2; k <= HH; k <<= 1) {
        bool up = ((e0 & k) == 0);
        for (int j = k >> 1; j >= 64; j >>= 1) {
            sk[e0] = k0; sk[e1] = k1;
            __syncthreads();
            ull p0 = sk[e0 ^ j], p1 = sk[e1 ^ j];
            bool takeMin = (up == ((e0 & j) == 0));
            k0 = cmpx(k0, p0, takeMin);
            k1 = cmpx(k1, p1, takeMin);
            __syncthreads();
        }
        int jstart = ((k >> 1) < 32) ? (k >> 1) : 32;
        for (int j = jstart; j >= 2; j >>= 1) {
            ull p0 = __shfl_xor_sync(0xffffffffu, k0, j >> 1);
            ull p1 = __shfl_xor_sync(0xffffffffu, k1, j >> 1);
            bool takeMin = (up == ((e0 & j) == 0));
            k0 = cmpx(k0, p0, takeMin);
            k1 = cmpx(k1, p1, takeMin);
        }
        {
            ull lo = k0 < k1 ? k0 : k1;
            ull hi = k0 < k1 ? k1 : k0;
            k0 = up ? lo : hi;
            k1 = up ? hi : lo;
        }
    }

    int tok0 = (int)(k0 & 0xFFFFFFFFu);
    int tok1 = (int)(k1 & 0xFFFFFFFFu);
    if (e0 >= RR) g_unm[b * NU + (e0 - RR)] = tok0;
    if (e1 >= RR) g_unm[b * NU + (e1 - RR)] = tok1;

    // ---- CSR build: dst -> list of src tokens ----
    cnt[e0] = 0; cnt[e1] = 0;
    __syncthreads();
    int d0 = -1, d1 = -1;
    if (e0 < RR) { d0 = nidx[tok0]; atomicAdd(&cnt[d0], 1); }
    if (e1 < RR) { d1 = nidx[tok1]; atomicAdd(&cnt[d1], 1); }
    __syncthreads();
    int* bufA = (int*)sk;
    int* bufB = bufA + HH;
    bufA[e0] = cnt[e0]; bufA[e1] = cnt[e1];
    __syncthreads();
    for (int d = 1; d < HH; d <<= 1) {
        for (int t = tid; t < HH; t += 512)
            bufB[t] = bufA[t] + (t >= d ? bufA[t - d] : 0);
        __syncthreads();
        int* tmp = bufA; bufA = bufB; bufB = tmp;
    }
    for (int t = tid; t < HH; t += 512) {
        int ex = bufA[t] - cnt[t];
        off[t] = ex;
        g_cnt[b * HH + t] = cnt[t];
        g_off[b * HH + t] = ex;
        bufB[t] = 0;
    }
    __syncthreads();
    if (e0 < RR) { int pos = off[d0] + atomicAdd(&bufB[d0], 1); g_csr[b * RR + pos] = tok0; }
    if (e1 < RR) { int pos = off[d1] + atomicAdd(&bufB[d1], 1); g_csr[b * RR + pos] = tok1; }
}

// ---------------- fused assembly: gather + merge-sum + divide + source ones ----------------
__global__ __launch_bounds__(256) void assemble_kernel(const float* __restrict__ x,
                                                       float* __restrict__ out) {
    int w = (blockIdx.x * 256 + threadIdx.x) >> 5;   // 0..12287
    int lane = threadIdx.x & 31;
    int b = w / LO, k = w % LO;
    float* osrc = out + (size_t)BB * LO * DD;

    if (k < NU) {
        int t = g_unm[b * NU + k];
        const float4* src = (const float4*)(x + ((size_t)b * LL + 2 * t) * DD);
        float4* dst = (float4*)(out + ((size_t)b * LO + k) * DD);
#pragma unroll
        for (int p = 0; p < 4; p++) dst[lane + 32 * p] = src[lane + 32 * p];
        if (lane == 0)
            osrc[((size_t)b * LO + k) * LL + 2 * t] = 1.0f;
    } else {
        int j = k - NU;
        const float4* base = (const float4*)(x + ((size_t)b * LL + 2 * j + 1) * DD);
        float4 v[4];
#pragma unroll
        for (int p = 0; p < 4; p++) v[p] = base[lane + 32 * p];
        int c = g_cnt[b * HH + j];
        int o = g_off[b * HH + j];
        for (int i = 0; i < c; i++) {
            int s = g_csr[b * RR + o + i];
            const float4* sr = (const float4*)(x + ((size_t)b * LL + 2 * s) * DD);
#pragma unroll
            for (int p = 0; p < 4; p++) {
                float4 u = sr[lane + 32 * p];
                v[p].x = __fadd_rn(v[p].x, u.x);
                v[p].y = __fadd_rn(v[p].y, u.y);
                v[p].z = __fadd_rn(v[p].z, u.z);
                v[p].w = __fadd_rn(v[p].w, u.w);
            }
        }
        if (c > 0) {
            float den = (float)(c + 1);
#pragma unroll
            for (int p = 0; p < 4; p++) {
                v[p].x = __fdiv_rn(v[p].x, den);
                v[p].y = __fdiv_rn(v[p].y, den);
                v[p].z = __fdiv_rn(v[p].z, den);
                v[p].w = __fdiv_rn(v[p].w, den);
            }
        }
        float4* dst = (float4*)(out + ((size_t)b * LO + k) * DD);
#pragma unroll
        for (int p = 0; p < 4; p++) dst[lane + 32 * p] = v[p];

        float* srow = &osrc[((size_t)b * LO + k) * LL];
        if (lane == 0) srow[2 * j + 1] = 1.0f;
        for (int i = lane; i < c; i += 32)
            srow[2 * g_csr[b * RR + o + i]] = 1.0f;
    }
}

// ---------------- launch ----------------
extern "C" void kernel_launch(void* const* d_in, const int* in_sizes, int n_in,
                              void* d_out, int out_size) {
    const float* x = (const float*)d_in[0];
    const float* W = (const float*)d_in[1];
    const int* mask = (const int*)d_in[2];
    float* out = (float*)d_out;

    (void)in_sizes; (void)n_in; (void)out_size;

    static cudaStream_t s2 = nullptr;
    static cudaEvent_t evFork = nullptr, evJoin = nullptr;
    static bool attrs_set = false;
    if (!s2) {
        cudaStreamCreateWithFlags(&s2, cudaStreamNonBlocking);
        cudaEventCreateWithFlags(&evFork, cudaEventDisableTiming);
        cudaEventCreateWithFlags(&evJoin, cudaEventDisableTiming);
    }
    int metric_smem = 2 * TILE_F * (int)sizeof(float);                // 70656 B
    int scores_smem = (128 * AST2 + 128 * BST2) * (int)sizeof(float); // 135168 B
    if (!attrs_set) {
        cudaFuncSetAttribute(metric_kernel, cudaFuncAttributeMaxDynamicSharedMemorySize,
                             metric_smem);
        cudaFuncSetAttribute(scores_kernel, cudaFuncAttributeMaxDynamicSharedMemorySize,
                             scores_smem);
        attrs_set = true;
    }

    // fork: zero the 100MB source region on s2, overlapped with the FMA-bound GEMMs
    cudaEventRecord(evFork, 0);
    cudaStreamWaitEvent(s2, evFork, 0);
    cudaMemsetAsync(out + (size_t)BB * LO * DD, 0,
                    (size_t)BB * LO * LL * sizeof(float), s2);
    cudaEventRecord(evJoin, s2);

    metric_kernel<<<(BB * LL) / 128, 512, metric_smem>>>(x, W);
    scores_kernel<<<BB * 8 * 2, 512, scores_smem>>>(mask);
    sort_kernel<<<BB, 512>>>();

    cudaStreamWaitEvent(0, evJoin, 0);
    assemble_kernel<<<BB * LO / 8, 256>>>(x, out);
}